// round 13
// baseline (speedup 1.0000x reference)
#include <cuda_runtime.h>
#include <cuda_bf16.h>

// SpatialConsistencyLoss — single launch, producer/consumer with PER-IMAGE
// completion counters so the loss phase overlaps the stream.
//   original, enhanced: [32,3,512,512] f32
//   p = avg_pool4(mean_c(orig)) - avg_pool4(mean_c(enh))   [32,128,128]
//   loss[i,j] = sum_dirs (p[i,j] - p[nbr])^2, zero-padded  -> [32,1,128,128]
//
// R12 evidence: kernel = 31.6us stream + ~5us exposed consumer tail (2MB
// scratch read, DRAM-latency-bound). Root cause: consumers waited on ALL
// 2048 producers. Loss of image b depends only on image b's 64 producer
// blocks (low bids, finish early) -> wait on counter[b]==64 instead. Loss
// work then executes DURING the stream; only the last image's consumers
// (~0.3us) stay exposed, and their 4MB of traffic amortizes into the
// bandwidth-bound stream (+0.6us) instead of serializing (+5us).
//
// Deadlock-free: 512 consumers (highest bids, scheduled last) can never
// starve 2048 producers (~1184-block chip capacity => >=672 producer slots
// always). Counters self-reset => graph-replay deterministic.

#define B 32
#define HP 128
#define WP 128
#define NPOOL (B * HP * WP)   // 524288
#define HIN 512
#define WIN 512
#define CH_STRIDE (HIN * WIN)          // 262144
#define IMG_STRIDE (3 * CH_STRIDE)     // 786432
#define THREADS 256
#define POOL_BLOCKS (NPOOL / THREADS)        // 2048 (64 per image)
#define LOSS_BLOCKS (NPOOL / 4 / THREADS)    // 512  (16 per image)
#define PROD_PER_IMG (POOL_BLOCKS / B)       // 64

__device__ float g_pooled[NPOOL];            // 2 MB scratch
__device__ unsigned int g_img_done[B];       // per-image producer counters
__device__ unsigned int g_exit = 0;          // consumer exit counter (reset)

__device__ __forceinline__ float sq(float x) { return x * x; }

__global__ void scl_imgsync_kernel(const float* __restrict__ orig,
                                   const float* __restrict__ enh,
                                   float* __restrict__ out) {
    if (blockIdx.x < POOL_BLOCKS) {
        // ================= Producer: streaming pool block =================
        int idx = blockIdx.x * THREADS + threadIdx.x;

        int j = idx & (WP - 1);
        int i = (idx >> 7) & (HP - 1);
        int b = idx >> 14;                    // image; == blockIdx.x / 64

        int base0 = b * IMG_STRIDE + (i * 4) * WIN + (j * 4);

        float s = 0.0f;
#pragma unroll
        for (int c = 0; c < 3; ++c) {
            int base = base0 + c * CH_STRIDE;
#pragma unroll
            for (int r = 0; r < 4; ++r) {
                float4 ov = __ldcs(reinterpret_cast<const float4*>(orig + base + r * WIN));
                float4 ev = __ldcs(reinterpret_cast<const float4*>(enh  + base + r * WIN));
                s += (ov.x - ev.x) + (ov.y - ev.y) + (ov.z - ev.z) + (ov.w - ev.w);
            }
        }
        g_pooled[idx] = s * (1.0f / 48.0f);   // /3 channels, /16 pool

        __syncthreads();
        if (threadIdx.x == 0) {
            __threadfence();                  // release this block's scratch
            atomicAdd(&g_img_done[b], 1u);
        }
        // Block retires; slot freed for the remaining stream.
    } else {
        // ================= Consumer: per-image loss block =================
        int cb  = blockIdx.x - POOL_BLOCKS;   // 0..511
        int img = cb >> 4;                    // 16 consumer blocks per image

        if (threadIdx.x == 0) {
            while (*(volatile unsigned int*)&g_img_done[img] < PROD_PER_IMG) { }
            __threadfence();                  // acquire this image's scratch
        }
        __syncthreads();

        int t = cb * THREADS + threadIdx.x;   // quad index, 0 .. NPOOL/4-1

        int j4  = (t & 31) << 2;              // first j of the 4-wide quad
        int row = t >> 5;                     // b*128 + i
        int i   = row & (HP - 1);
        int base = (row << 7) + j4;

        const float4* p4 = reinterpret_cast<const float4*>(g_pooled);
        float4 c  = p4[base >> 2];
        float4 up = (i > 0)      ? p4[(base - WP) >> 2] : make_float4(0.f, 0.f, 0.f, 0.f);
        float4 dn = (i < HP - 1) ? p4[(base + WP) >> 2] : make_float4(0.f, 0.f, 0.f, 0.f);
        float left  = (j4 > 0)      ? g_pooled[base - 1] : 0.f;
        float right = (j4 < WP - 4) ? g_pooled[base + 4] : 0.f;

        float4 o;
        o.x = sq(c.x - left) + sq(c.x - c.y)   + sq(c.x - up.x) + sq(c.x - dn.x);
        o.y = sq(c.y - c.x)  + sq(c.y - c.z)   + sq(c.y - up.y) + sq(c.y - dn.y);
        o.z = sq(c.z - c.y)  + sq(c.z - c.w)   + sq(c.z - up.z) + sq(c.z - dn.z);
        o.w = sq(c.w - c.z)  + sq(c.w - right) + sq(c.w - up.w) + sq(c.w - dn.w);

        reinterpret_cast<float4*>(out)[base >> 2] = o;

        // -------- Reset counters for the next graph replay --------
        __syncthreads();
        if (threadIdx.x == 0) {
            unsigned int old = atomicAdd(&g_exit, 1u);
            if (old == LOSS_BLOCKS - 1) {     // last consumer resets everything
#pragma unroll
                for (int k = 0; k < B; ++k)
                    atomicExch(&g_img_done[k], 0u);
                atomicExch(&g_exit, 0u);
            }
        }
    }
}

extern "C" void kernel_launch(void* const* d_in, const int* in_sizes, int n_in,
                              void* d_out, int out_size) {
    const float* orig = (const float*)d_in[0];
    const float* enh  = (const float*)d_in[1];
    float* out = (float*)d_out;

    scl_imgsync_kernel<<<POOL_BLOCKS + LOSS_BLOCKS, THREADS>>>(orig, enh, out);
}